// round 7
// baseline (speedup 1.0000x reference)
#include <cuda_runtime.h>

// MultiStageFIRFilter: y = x + sum_{a=1..20} xa_a,
//   xa_a[b,t] = (1/a) * sum_{k=0..24} mc[b,t,k] * xa_{a-1}[b,t-k]  (xa_0 = x, causal)
//
// Fused halo-recompute kernel, warp-pipelined with NO block barrier in the
// stage loop and NO anti-dependency waits: 21 stage buffers in dynamic smem
// (each written exactly once). Warp w consumes warp w+1's output (w+1 is its
// spatial LEFT neighbor under the reversed mapping), so the lead producer is
// warp 7 -> highest arbiter priority (hi-wid-first). Lane 0 spins, warp follows.

#define NB      4
#define NT      16384
#define M       25
#define STAGES  20
#define HALO    480       // STAGES * 24
#define THREADS 256
#define R       4
#define EXT     1024      // THREADS * R
#define TILE    544       // EXT - HALO
#define PAD     24
#define NTILES  31        // ceil(16384 / 544)
#define NWARP   8
#define SLOT    (PAD + EXT)                 // 1048 floats per stage buffer
#define SMEM_FLOATS ((STAGES + 1) * SLOT)   // 21 buffers
#define SMEM_BYTES  (SMEM_FLOATS * 4 + 32)  // + flags

__device__ __forceinline__ void flag_release(int* p, int v) {
    asm volatile("st.release.cta.b32 [%0], %1;" :: "l"(p), "r"(v) : "memory");
}
__device__ __forceinline__ int flag_acquire(const int* p) {
    int v;
    asm volatile("ld.acquire.cta.b32 %0, [%1];" : "=r"(v) : "l"(p) : "memory");
    return v;
}

__global__ __launch_bounds__(THREADS, 1)
void fir_kernel(const float* __restrict__ x, const float* __restrict__ mc,
                float* __restrict__ out)
{
    extern __shared__ __align__(16) float sm[];
    int* flags = (int*)(sm + SMEM_FLOATS);   // flags[w] = last stage warp w completed

    const int tile = blockIdx.x % NTILES;
    const int b    = blockIdx.x / NTILES;
    const int t0   = tile * TILE;
    const int tid  = threadIdx.x;
    const int w    = tid >> 5;
    const int lane = tid & 31;
    // Reversed spatial mapping: warp 7 owns the leftmost 128 positions (the
    // dependency-free lead producer), warp 0 the rightmost.
    const int i0   = R * (32 * (NWARP - 1 - w) + lane);   // multiple of 4
    const int p0   = t0 - HALO + i0;                      // global time (mult of 4)
    const size_t rowbase = (size_t)b * NT;
    const bool valid = (p0 >= 0 && p0 + R - 1 < NT);      // rows all-valid or all-not

    // zero the PAD region of all 21 buffers; init flags
    for (int idx = tid; idx < (STAGES + 1) * PAD; idx += THREADS) {
        sm[(idx / PAD) * SLOT + (idx % PAD)] = 0.0f;
    }
    if (tid < NWARP) flags[tid] = 0;

    // ---- coefficients: c[25*r + k] = mc[p0+r][k] (contiguous, 16B-aligned) ----
    // Invalid rows get c = 0 -> acc = 0 exactly (covers ghosts p<0 and p>=NT).
    float c[100];
    if (valid) {
        const float4* g = (const float4*)(mc + (rowbase + (size_t)p0) * M);
        #pragma unroll
        for (int k = 0; k < 25; k++) {
            float4 v4 = g[k];
            c[4*k] = v4.x; c[4*k+1] = v4.y; c[4*k+2] = v4.z; c[4*k+3] = v4.w;
        }
    } else {
        #pragma unroll
        for (int j = 0; j < 100; j++) c[j] = 0.0f;
    }

    // ---- stage 0: xa = x ----
    float v[R], y[R];
    if (valid) {
        const float4 xv = *(const float4*)(x + rowbase + p0);
        v[0] = xv.x; v[1] = xv.y; v[2] = xv.z; v[3] = xv.w;
    } else {
        #pragma unroll
        for (int r = 0; r < R; r++) v[r] = 0.0f;
    }
    #pragma unroll
    for (int r = 0; r < R; r++) y[r] = v[r];

    *((float4*)(sm + PAD + i0)) = make_float4(v[0], v[1], v[2], v[3]);  // buf 0
    __syncthreads();   // stage-0 data + flag init + PAD zeros visible

    #pragma unroll
    for (int a = 1; a <= STAGES; a++) {
        const float inv = 1.0f / (float)a;            // compile-time constant
        // wait: left-neighbor warp (w+1) finished stage a-1 (warp 7 waits on no one)
        if (w < NWARP - 1) {
            if (lane == 0) while (flag_acquire(&flags[w + 1]) < a - 1) {}
            __syncwarp();
        }

        const float* cur = sm + (a - 1) * SLOT;
        // w24[j] = xa_{a-1}[position i0-24+j]; position q at buffer index PAD+q,
        // so the window starts at cur + i0 (16B-aligned).
        float w24[24];
        const float4* wp = (const float4*)(cur + i0);
        #pragma unroll
        for (int j = 0; j < 6; j++) {
            float4 q = wp[j];
            w24[4*j] = q.x; w24[4*j+1] = q.y; w24[4*j+2] = q.z; w24[4*j+3] = q.w;
        }

        float acc[R];
        #pragma unroll
        for (int r = 0; r < R; r++) {
            float pA = 0.0f, pB = 0.0f;               // two independent chains
            #pragma unroll
            for (int k = 0; k <= 12; k++) {
                const int d = r - k;
                const float val = (d >= 0) ? v[d] : w24[24 + d];
                pA = fmaf(c[25*r + k], val, pA);
            }
            #pragma unroll
            for (int k = 13; k <= 24; k++) {
                pB = fmaf(c[25*r + k], w24[24 + r - k], pB);
            }
            acc[r] = (pA + pB) * inv;
        }
        #pragma unroll
        for (int r = 0; r < R; r++) { y[r] += acc[r]; v[r] = acc[r]; }
        *((float4*)(sm + a * SLOT + PAD + i0)) = make_float4(v[0], v[1], v[2], v[3]);

        __syncwarp();                                 // lanes' stores precede release
        if (lane == 0) flag_release(&flags[w], a);
    }

    // ---- write owned (non-halo) outputs ----
    if (i0 >= HALO && p0 < NT) {
        if (p0 + R - 1 < NT) {
            *((float4*)(out + rowbase + p0)) = make_float4(y[0], y[1], y[2], y[3]);
        } else {
            #pragma unroll
            for (int r = 0; r < R; r++)
                if (p0 + r < NT) out[rowbase + p0 + r] = y[r];
        }
    }
}

extern "C" void kernel_launch(void* const* d_in, const int* in_sizes, int n_in,
                              void* d_out, int out_size)
{
    const float* x  = (const float*)d_in[0];   // (4, 16384) float32
    const float* mc = (const float*)d_in[1];   // (4, 16384, 25) float32
    float* out = (float*)d_out;                // (4, 16384) float32
    static int configured = 0;
    if (!configured) {
        cudaFuncSetAttribute(fir_kernel, cudaFuncAttributeMaxDynamicSharedMemorySize,
                             SMEM_BYTES);
        configured = 1;
    }
    fir_kernel<<<NB * NTILES, THREADS, SMEM_BYTES>>>(x, mc, out);
}

// round 8
// speedup vs baseline: 1.1629x; 1.1629x over previous
#include <cuda_runtime.h>

// MultiStageFIRFilter: y = x + sum_{a=1..20} xa_a,
//   xa_a[b,t] = (1/a) * sum_{k=0..24} mc[b,t,k] * xa_{a-1}[b,t-k]  (xa_0 = x, causal)
//
// Fused halo-recompute kernel, 512 threads, R=2, barrier per stage (best
// measured convoy behavior), with packed fma.rn.f32x2 over tap pairs.
// Stage buffers are stored TIME-REVERSED: rev[1024 - p] = val(p). Then the
// operand pair for taps (k,k+1) of output p, (val(p-k), val(p-k-1)), is a
// naturally-aligned ascending float2 — no MOV packing, and outputs i0 / i0+1
// (tap-paired with opposite k parity) share the same 13 float2 loads.

#define NB      4
#define NT      16384
#define M       25
#define STAGES  20
#define HALO    480       // STAGES * 24
#define THREADS 512
#define EXT     1024      // 2 positions per thread
#define TILE    544       // EXT - HALO
#define NTILES  31        // ceil(16384 / 544)
#define RSZ     1056      // reversed buffer: idx = 1024 - p, p in [-27, 1024)

__device__ __forceinline__ unsigned long long fma2(unsigned long long a,
                                                   unsigned long long b,
                                                   unsigned long long c) {
    unsigned long long d;
    asm("fma.rn.f32x2 %0, %1, %2, %3;" : "=l"(d) : "l"(a), "l"(b), "l"(c));
    return d;
}
__device__ __forceinline__ unsigned long long pack2(float lo, float hi) {
    unsigned long long d;
    asm("mov.b64 %0, {%1, %2};" : "=l"(d) : "f"(lo), "f"(hi));
    return d;
}
__device__ __forceinline__ void unpack2(unsigned long long v, float& lo, float& hi) {
    asm("mov.b64 {%0, %1}, %2;" : "=f"(lo), "=f"(hi) : "l"(v));
}

__global__ __launch_bounds__(THREADS, 1)
void fir_kernel(const float* __restrict__ x, const float* __restrict__ mc,
                float* __restrict__ out)
{
    __shared__ __align__(16) float rev0[RSZ];
    __shared__ __align__(16) float rev1[RSZ];

    const int tile = blockIdx.x % NTILES;
    const int b    = blockIdx.x / NTILES;
    const int t0   = tile * TILE;
    const int tid  = threadIdx.x;
    const int i0   = 2 * tid;              // local position (even)
    const int p0   = t0 - HALO + i0;       // global time of first owned position
    const size_t rowbase = (size_t)b * NT;
    const bool valid = (p0 >= 0 && p0 + 1 < NT);   // p0 even -> both rows or neither

    // ghost region (local p < 0): idx 1025..1055, plus unused idx 0
    if (tid < 32) {
        const int gi = (tid < 31) ? (1025 + tid) : 0;
        rev0[gi] = 0.0f; rev1[gi] = 0.0f;
    }

    // ---- coefficients (rows p0, p0+1 = 50 contiguous floats), then tap-pair pack.
    // Invalid rows get c = 0 -> acc = 0 exactly (covers global ghosts / overhang).
    float c0[25], c1[25];
    if (valid) {
        const float2* g = (const float2*)(mc + (rowbase + (size_t)p0) * M);  // 8B-aligned
        float t[50];
        #pragma unroll
        for (int k = 0; k < 25; k++) { float2 v2 = g[k]; t[2*k] = v2.x; t[2*k+1] = v2.y; }
        #pragma unroll
        for (int k = 0; k < 25; k++) { c0[k] = t[k]; c1[k] = t[25 + k]; }
    } else {
        #pragma unroll
        for (int k = 0; k < 25; k++) { c0[k] = 0.0f; c1[k] = 0.0f; }
    }
    // out0 tap pairs: (c0[2j], c0[2j+1]) j=0..11, leftover c0[24]
    // out1 tap pairs: (c1[2j+1], c1[2j+2]) j=0..11, leftover c1[0]
    unsigned long long cp0[12], cp1[12];
    #pragma unroll
    for (int j = 0; j < 12; j++) {
        cp0[j] = pack2(c0[2*j],     c0[2*j + 1]);
        cp1[j] = pack2(c1[2*j + 1], c1[2*j + 2]);
    }
    const float c0e = c0[24];
    const float c1e = c1[0];

    // ---- stage 0: xa = x ----
    float v1, y0, y1;
    {
        float v0;
        if (valid) {
            const float2 xv = *(const float2*)(x + rowbase + p0);
            v0 = xv.x; v1 = xv.y;
        } else { v0 = 0.0f; v1 = 0.0f; }
        y0 = v0; y1 = v1;
        rev0[1024 - i0] = v0;          // val(i0)
        rev0[1023 - i0] = v1;          // val(i0+1)
    }
    __syncthreads();

    float* cur = rev0;
    float* nxt = rev1;

    #pragma unroll
    for (int a = 1; a <= STAGES; a++) {
        const float inv = 1.0f / (float)a;          // compile-time constant
        if (tid >= 12 * a) {                        // exactness trim (pos >= 24a)
            // L[j] = (val(i0-2j), val(i0-2j-1)), j = 0..12; q = 1024-i0+2j, even, 8B-aligned
            float2 L[13];
            const float2* Lp = (const float2*)(cur + (1024 - i0));
            #pragma unroll
            for (int j = 0; j < 13; j++) L[j] = Lp[j];

            unsigned long long A0 = 0ull, B0 = 0ull, A1 = 0ull, B1 = 0ull;
            #pragma unroll
            for (int j = 0; j < 6; j++) {
                const unsigned long long Lv = pack2(L[j].x, L[j].y);  // reg alias
                A0 = fma2(cp0[j], Lv, A0);
                A1 = fma2(cp1[j], Lv, A1);
            }
            #pragma unroll
            for (int j = 6; j < 12; j++) {
                const unsigned long long Lv = pack2(L[j].x, L[j].y);
                B0 = fma2(cp0[j], Lv, B0);
                B1 = fma2(cp1[j], Lv, B1);
            }
            float a0l, a0h, b0l, b0h, a1l, a1h, b1l, b1h;
            unpack2(A0, a0l, a0h); unpack2(B0, b0l, b0h);
            unpack2(A1, a1l, a1h); unpack2(B1, b1l, b1h);

            // out0: even taps in .lo, odd taps in .hi, leftover k=24 uses val(i0-24)=L[12].x
            const float out0 = fmaf(c0e, L[12].x, (a0l + b0l) + (a0h + b0h)) * inv;
            // out1: odd taps in .lo, even taps in .hi, leftover k=0 uses val(i0+1)=v1
            const float out1 = fmaf(c1e, v1, (a1l + b1l) + (a1h + b1h)) * inv;

            y0 += out0; y1 += out1; v1 = out1;
            nxt[1024 - i0] = out0;
            nxt[1023 - i0] = out1;
        }
        __syncthreads();
        float* tmp = cur; cur = nxt; nxt = tmp;
    }

    // ---- write owned (non-halo) outputs ----
    if (i0 >= HALO && p0 < NT) {                    // valid here by construction
        *(float2*)(out + rowbase + p0) = make_float2(y0, y1);
    }
}

extern "C" void kernel_launch(void* const* d_in, const int* in_sizes, int n_in,
                              void* d_out, int out_size)
{
    const float* x  = (const float*)d_in[0];   // (4, 16384) float32
    const float* mc = (const float*)d_in[1];   // (4, 16384, 25) float32
    float* out = (float*)d_out;                // (4, 16384) float32
    fir_kernel<<<NB * NTILES, THREADS>>>(x, mc, out);
}